// round 16
// baseline (speedup 1.0000x reference)
#include <cuda_runtime.h>
#include <cuda_bf16.h>
#include <cstddef>

#define T_STEPS 2048
#define BATCH   64
#define HID     128
#define GATES   512          // 4*HID
#define RK      96           // k-values in registers (as pairs)
#define RKP     (RK/2)       // 48 register pairs
#define SK      (HID - RK)   // 32 k-values in smem
#define SKP     (SK/2)       // 16 smem pairs
#define NSM     148
#define NCHUNK  16           // 2048 / 128
#define CHSTEP  128
#define NTASK   (2 * NCHUNK * BATCH * 4)   // 8192 tiles across both inner GEMMs

typedef unsigned long long ull;

// ---- packed fp32x2 helpers (sm_100+) --------------------------------------
__device__ __forceinline__ ull ffma2(ull a, ull b, ull c) {
    ull d;
    asm("fma.rn.f32x2 %0, %1, %2, %3;" : "=l"(d) : "l"(a), "l"(b), "l"(c));
    return d;
}
__device__ __forceinline__ ull pack2(float lo, float hi) {
    ull r; asm("mov.b64 %0, {%1, %2};" : "=l"(r) : "f"(lo), "f"(hi)); return r;
}
__device__ __forceinline__ float2 unpack2(ull v) {
    float2 f; asm("mov.b64 {%0, %1}, %2;" : "=f"(f.x), "=f"(f.y) : "l"(v)); return f;
}
__device__ __forceinline__ int ld_acquire_gpu(const int* p) {
    int v;
    asm volatile("ld.acquire.gpu.global.s32 %0, [%1];" : "=r"(v) : "l"(p) : "memory");
    return v;
}

// Scratch (device globals; no allocations allowed)
__device__ float g_gxA[(size_t)BATCH * T_STEPS * GATES];  // gx0, then reused for gx2
__device__ float g_gxB[(size_t)BATCH * T_STEPS * GATES];  // gx1
__device__ __nv_bfloat16 g_xhi[(size_t)BATCH * T_STEPS * HID];  // x split
__device__ __nv_bfloat16 g_xlo[(size_t)BATCH * T_STEPS * HID];
__device__ __nv_bfloat16 g_h0hi[(size_t)BATCH * T_STEPS * HID]; // h0 split
__device__ __nv_bfloat16 g_h0lo[(size_t)BATCH * T_STEPS * HID];
__device__ __nv_bfloat16 g_h1hi[(size_t)BATCH * T_STEPS * HID]; // h1 split
__device__ __nv_bfloat16 g_h1lo[(size_t)BATCH * T_STEPS * HID];
__device__ __nv_bfloat16 g_whi[3 * GATES * HID];                // wih split (3 layers)
__device__ __nv_bfloat16 g_wlo[3 * GATES * HID];
__device__ float g_h2last[BATCH * HID];
__device__ int   g_syn[130 + BATCH * NCHUNK * 2];  // prog0[64] prog1[64] ctr _ chunk1 chunk2

// ---------------------------------------------------------------------------
// fp32 -> (bf16 hi, bf16 lo) splitter, vectorized 4 elements/thread
// ---------------------------------------------------------------------------
__global__ __launch_bounds__(256) void split_kernel(
    const float* __restrict__ src, __nv_bfloat16* __restrict__ hi,
    __nv_bfloat16* __restrict__ lo, long n4)
{
    long i = (long)blockIdx.x * 256 + threadIdx.x;
    if (i >= n4) return;
    float4 v = ((const float4*)src)[i];
    __nv_bfloat16 h0 = __float2bfloat16_rn(v.x);
    __nv_bfloat16 h1 = __float2bfloat16_rn(v.y);
    __nv_bfloat16 h2 = __float2bfloat16_rn(v.z);
    __nv_bfloat16 h3 = __float2bfloat16_rn(v.w);
    __nv_bfloat162 H0; H0.x = h0; H0.y = h1;
    __nv_bfloat162 H1; H1.x = h2; H1.y = h3;
    __nv_bfloat162 L0 = __floats2bfloat162_rn(v.x - __bfloat162float(h0),
                                              v.y - __bfloat162float(h1));
    __nv_bfloat162 L1 = __floats2bfloat162_rn(v.z - __bfloat162float(h2),
                                              v.w - __bfloat162float(h3));
    ((__nv_bfloat162*)hi)[2 * i]     = H0;
    ((__nv_bfloat162*)hi)[2 * i + 1] = H1;
    ((__nv_bfloat162*)lo)[2 * i]     = L0;
    ((__nv_bfloat162*)lo)[2 * i + 1] = L1;
}

// ---------------------------------------------------------------------------
// GEMM tile (pre-split bf16 inputs, fp32 acc, ldmatrix). Load phase is pure
// vector copy gmem->smem — no conversion.
// ---------------------------------------------------------------------------
#define SR 136   // padded bf16 row stride

__device__ __forceinline__ void mma_bf16(float* d, const unsigned* a, const unsigned* b) {
    asm volatile(
        "mma.sync.aligned.m16n8k16.row.col.f32.bf16.bf16.f32 "
        "{%0,%1,%2,%3}, {%4,%5,%6,%7}, {%8,%9}, {%0,%1,%2,%3};"
        : "+f"(d[0]), "+f"(d[1]), "+f"(d[2]), "+f"(d[3])
        : "r"(a[0]), "r"(a[1]), "r"(a[2]), "r"(a[3]), "r"(b[0]), "r"(b[1]));
}
__device__ __forceinline__ void ldsm_x4(unsigned* r, unsigned addr) {
    asm volatile("ldmatrix.sync.aligned.m8n8.x4.shared.b16 {%0,%1,%2,%3}, [%4];"
                 : "=r"(r[0]), "=r"(r[1]), "=r"(r[2]), "=r"(r[3]) : "r"(addr));
}

__device__ void gemm_tile(const __nv_bfloat16* __restrict__ Ahi,
                          const __nv_bfloat16* __restrict__ Alo,
                          const __nv_bfloat16* __restrict__ Whi,
                          const __nv_bfloat16* __restrict__ Wlo,
                          const float* __restrict__ bih, const float* __restrict__ bhh,
                          float* __restrict__ out, int brow, int bcol, char* gsm)
{
    __nv_bfloat16* a_hi = (__nv_bfloat16*)gsm;                  // [128][SR]
    __nv_bfloat16* a_lo = a_hi + 128 * SR;
    __nv_bfloat16* w_hi = a_lo + 128 * SR;
    __nv_bfloat16* w_lo = w_hi + 128 * SR;
    float*         bias_s = (float*)(w_lo + 128 * SR);          // [128]

    const int tid = threadIdx.x;
    if (tid < 128) bias_s[tid] = bih[bcol + tid] + bhh[bcol + tid];

    // ---- pure copy phase: 4 x 128B per thread ----
    {
        const int row = tid >> 1;
        const int cb  = (tid & 1) * 64;
        const uint4* sAh = (const uint4*)(Ahi + (size_t)(brow + row) * HID + cb);
        const uint4* sAl = (const uint4*)(Alo + (size_t)(brow + row) * HID + cb);
        const uint4* sWh = (const uint4*)(Whi + (size_t)(bcol + row) * HID + cb);
        const uint4* sWl = (const uint4*)(Wlo + (size_t)(bcol + row) * HID + cb);
        uint4* dAh = (uint4*)(a_hi + row * SR + cb);
        uint4* dAl = (uint4*)(a_lo + row * SR + cb);
        uint4* dWh = (uint4*)(w_hi + row * SR + cb);
        uint4* dWl = (uint4*)(w_lo + row * SR + cb);
#pragma unroll
        for (int i = 0; i < 8; i++) {
            dAh[i] = sAh[i];
            dAl[i] = sAl[i];
            dWh[i] = sWh[i];
            dWl[i] = sWl[i];
        }
    }
    __syncthreads();

    const int wid    = tid >> 5;
    const int lane   = tid & 31;
    const int warp_m = wid >> 1;
    const int warp_n = wid & 1;
    const int m_base = warp_m * 32;
    const int n_base = warp_n * 64;

    const unsigned a_hi_s = (unsigned)__cvta_generic_to_shared(a_hi);
    const unsigned a_lo_s = (unsigned)__cvta_generic_to_shared(a_lo);
    const unsigned w_hi_s = (unsigned)__cvta_generic_to_shared(w_hi);
    const unsigned w_lo_s = (unsigned)__cvta_generic_to_shared(w_lo);

    const int arow  = m_base + (lane & 15);
    const int akoff = (lane >> 4) * 8;
    const int gsel  = lane >> 3;
    const int brow_ = n_base + ((gsel >> 1) & 1) * 8 + (lane & 7);
    const int bkoff = (gsel & 1) * 8;

    float d[2][8][4];
#pragma unroll
    for (int mi = 0; mi < 2; mi++)
#pragma unroll
        for (int ni = 0; ni < 8; ni++)
#pragma unroll
            for (int e = 0; e < 4; e++) d[mi][ni][e] = 0.f;

#pragma unroll
    for (int k0 = 0; k0 < HID; k0 += 16) {
        unsigned ah[2][4], al[2][4];
#pragma unroll
        for (int mi = 0; mi < 2; mi++) {
            unsigned off = (unsigned)(((arow + mi * 16) * SR + akoff + k0) * 2);
            ldsm_x4(ah[mi], a_hi_s + off);
            ldsm_x4(al[mi], a_lo_s + off);
        }
        unsigned bh[4][4], bl[4][4];
#pragma unroll
        for (int nb = 0; nb < 4; nb++) {
            unsigned off = (unsigned)(((brow_ + nb * 16) * SR + bkoff + k0) * 2);
            ldsm_x4(bh[nb], w_hi_s + off);
            ldsm_x4(bl[nb], w_lo_s + off);
        }
#pragma unroll
        for (int mi = 0; mi < 2; mi++)
#pragma unroll
            for (int nb = 0; nb < 4; nb++) {
                mma_bf16(d[mi][2 * nb],     ah[mi], &bh[nb][0]);
                mma_bf16(d[mi][2 * nb],     ah[mi], &bl[nb][0]);
                mma_bf16(d[mi][2 * nb],     al[mi], &bh[nb][0]);
                mma_bf16(d[mi][2 * nb + 1], ah[mi], &bh[nb][2]);
                mma_bf16(d[mi][2 * nb + 1], ah[mi], &bl[nb][2]);
                mma_bf16(d[mi][2 * nb + 1], al[mi], &bh[nb][2]);
            }
    }

    const int tr = lane >> 2;
    const int tc = (lane & 3) * 2;
#pragma unroll
    for (int mi = 0; mi < 2; mi++) {
        int gr0 = brow + m_base + mi * 16 + tr;
#pragma unroll
        for (int ni = 0; ni < 8; ni++) {
            int lc = n_base + ni * 8 + tc;
            float2 bv = *(const float2*)&bias_s[lc];
            float2 o0 = {d[mi][ni][0] + bv.x, d[mi][ni][1] + bv.y};
            float2 o1 = {d[mi][ni][2] + bv.x, d[mi][ni][3] + bv.y};
            *(float2*)(out + (size_t)gr0 * GATES + bcol + lc)       = o0;
            *(float2*)(out + (size_t)(gr0 + 8) * GATES + bcol + lc) = o1;
        }
    }
}

// Standalone layer-0 GEMM over the whole (pre-split) input
__global__ __launch_bounds__(256) void gemm0_kernel(
    const float* __restrict__ bih, const float* __restrict__ bhh)
{
    extern __shared__ char gsm[];
    gemm_tile(g_xhi, g_xlo, g_whi, g_wlo, bih, bhh, g_gxA,
              blockIdx.x * 128, blockIdx.y * 128, gsm);
}

// ---------------------------------------------------------------------------
// Recurrence body (R3 structure, measured best).
// ---------------------------------------------------------------------------
__device__ __forceinline__ float sigm(float x) {
    return __fdividef(1.f, 1.f + __expf(-x));
}
__device__ __forceinline__ float tanh_fast(float x) {
    float e = __expf(2.f * x);
    return 1.f - __fdividef(2.f, e + 1.f);
}

__device__ void rec_body(const float* __restrict__ whh, const float* __restrict__ gx,
                         __nv_bfloat16* __restrict__ hhi, __nv_bfloat16* __restrict__ hlo,
                         float* __restrict__ hlast,
                         int* __restrict__ prog, const int* __restrict__ chunkready,
                         int b, char* smraw)
{
    ull*   ws2 = (ull*)smraw;                    // [SKP][512] pair-major weight pairs
    float* g_s = (float*)(ws2 + SKP * 512);      // 512 gate pre-activations
    float* h_s = g_s + GATES;                    // 128 hidden state

    const int tid = threadIdx.x;
    const int r0  = tid;
    const int r1  = tid + 256;

    ull wa2[RKP], wb2[RKP];
    {
        const ull* wp0 = (const ull*)(whh + (size_t)r0 * HID);
        const ull* wp1 = (const ull*)(whh + (size_t)r1 * HID);
#pragma unroll
        for (int q = 0; q < RKP; q++) { wa2[q] = wp0[q]; wb2[q] = wp1[q]; }
    }
    for (int idx = tid; idx < SKP * 512; idx += 256) {
        int r = idx & 511, p = idx >> 9;
        ws2[idx] = ((const ull*)(whh + (size_t)r * HID))[RKP + p];
    }
    if (tid < HID) h_s[tid] = 0.f;
    float c = 0.f;
    __syncthreads();

    const float* gxb = gx + (size_t)b * T_STEPS * GATES;
    __nv_bfloat16* hhib = hhi ? hhi + (size_t)b * T_STEPS * HID : nullptr;
    __nv_bfloat16* hlob = hlo ? hlo + (size_t)b * T_STEPS * HID : nullptr;

    float nga = 0.f, ngb = 0.f;
    if (!chunkready) { nga = gxb[r0]; ngb = gxb[r1]; }

    for (int t = 0; t < T_STEPS; t++) {
        if (chunkready && (t & (CHSTEP - 1)) == 0) {
            if (tid == 0) {
                const int* cw = chunkready + b * NCHUNK + (t >> 7);
                while (ld_acquire_gpu(cw) < 4) __nanosleep(128);
            }
            __syncthreads();
            nga = __ldg(gxb + (size_t)t * GATES + r0);
            ngb = __ldg(gxb + (size_t)t * GATES + r1);
        }
        ull acc0 = pack2(nga, 0.f);
        ull acc1 = pack2(ngb, 0.f);
        if (t + 1 < T_STEPS && (!chunkready || ((t + 1) & (CHSTEP - 1)) != 0)) {
            nga = __ldg(gxb + (size_t)(t + 1) * GATES + r0);
            ngb = __ldg(gxb + (size_t)(t + 1) * GATES + r1);
        }
        const ull* h2 = (const ull*)h_s;   // 64 packed h pairs (broadcast LDS.64)
#pragma unroll
        for (int q = 0; q < RKP; q++) {
            ull hp = h2[q];
            acc0 = ffma2(hp, wa2[q], acc0);
            acc1 = ffma2(hp, wb2[q], acc1);
        }
#pragma unroll
        for (int p = 0; p < SKP; p++) {
            ull hp = h2[RKP + p];
            acc0 = ffma2(hp, ws2[p * 512 + r0], acc0);
            acc1 = ffma2(hp, ws2[p * 512 + r1], acc1);
        }
        float2 v0 = unpack2(acc0);
        float2 v1 = unpack2(acc1);
        g_s[r0] = v0.x + v0.y;
        g_s[r1] = v1.x + v1.y;
        __syncthreads();
        if (tid < 128) {
            float i_ = sigm(g_s[tid]);
            float f_ = sigm(g_s[tid + 128]);
            float g_ = tanh_fast(g_s[tid + 256]);
            float o_ = sigm(g_s[tid + 384]);
            c = fmaf(f_, c, i_ * g_);
            float hv = o_ * tanh_fast(c);
            h_s[tid] = hv;
            if (hhib) {
                __nv_bfloat16 hb16 = __float2bfloat16_rn(hv);
                hhib[(size_t)t * HID + tid] = hb16;
                hlob[(size_t)t * HID + tid] =
                    __float2bfloat16_rn(hv - __bfloat162float(hb16));
            }
            if (hlast && t == T_STEPS - 1) hlast[b * HID + tid] = hv;
        }
        bool pub = prog && ((t & 63) == 63);
        if (pub) __threadfence();          // all threads: release h writes
        __syncthreads();
        if (pub && tid == 0) atomicExch(prog + b, t + 1);
    }
}

// ---------------------------------------------------------------------------
// Unified GEMM worker: ONE task queue over both inner GEMMs, statically
// interleaved in dependency-unlock order:
//   window 0:      gemm1 chunk 0
//   window 1..15:  gemm1 chunk w, then gemm2 chunk w-1
//   window 16:     gemm2 chunk 15
// gemm1 tiles gated on prog0 (rec0), gemm2 tiles on prog1 (rec1).
// ---------------------------------------------------------------------------
__device__ void gemm_worker_unified(
    const float* __restrict__ bih, const float* __restrict__ bhh,
    float* __restrict__ gx1, float* __restrict__ gx2,
    int* __restrict__ prog0, int* __restrict__ prog1,
    int* __restrict__ ctr, int* __restrict__ chunk1, int* __restrict__ chunk2,
    char* gsm)
{
    const int tid = threadIdx.x;
    const size_t WSZ = (size_t)GATES * HID;
    __shared__ int s_idx;
    while (true) {
        if (tid == 0) s_idx = atomicAdd(ctr, 1);
        __syncthreads();
        int idx = s_idx;
        __syncthreads();
        if (idx >= NTASK) break;

        int layer, chunk, t;
        if (idx < 256) { layer = 1; chunk = 0; t = idx; }
        else if (idx < NTASK - 256) {
            int r = idx - 256, pair = r >> 9, off = r & 511;
            if (off < 256) { layer = 1; chunk = pair + 1; t = off; }
            else           { layer = 2; chunk = pair;     t = off - 256; }
        } else { layer = 2; chunk = NCHUNK - 1; t = idx - (NTASK - 256); }
        int b  = t >> 2;
        int cy = t & 3;

        int* prog = (layer == 1) ? prog0 : prog1;
        if (tid == 0) {
            int need = (chunk + 1) * CHSTEP;
            int v;
            while (true) {
                asm volatile("ld.global.cg.u32 %0, [%1];" : "=r"(v) : "l"(prog + b));
                if (v >= need) break;
                __nanosleep(256);
            }
            __threadfence();
        }
        __syncthreads();
        if (layer == 1)
            gemm_tile(g_h0hi, g_h0lo, g_whi + WSZ, g_wlo + WSZ,
                      bih + GATES, bhh + GATES, gx1,
                      b * T_STEPS + chunk * CHSTEP, cy * 128, gsm);
        else
            gemm_tile(g_h1hi, g_h1lo, g_whi + 2 * WSZ, g_wlo + 2 * WSZ,
                      bih + 2 * GATES, bhh + 2 * GATES, gx2,
                      b * T_STEPS + chunk * CHSTEP, cy * 128, gsm);
        __threadfence();                 // all threads: release tile stores
        __syncthreads();
        if (tid == 0)
            atomicAdd(((layer == 1) ? chunk1 : chunk2) + b * NCHUNK + chunk, 1);
    }
}

// ---------------------------------------------------------------------------
// Mega kernel:
//  blocks [0,64):    rec0 (publishes prog0) -> rec2 (gated on chunk2)
//  blocks [64,128):  rec1 (gated on chunk1, publishes prog1) -> worker pool
//  blocks [128,148): unified worker pool
// gx2 aliases gx0's buffer — safe by the causal chain
// prog1>=128(k+1) => rec1 consumed gx1[k] => gemm1[k] done =>
// prog0>=128(k+1) => rec0 finished reading gx0[k].
// ---------------------------------------------------------------------------
__global__ __launch_bounds__(256, 1) void mega_kernel(
    const float* __restrict__ whh,
    const float* __restrict__ bih, const float* __restrict__ bhh,
    float* __restrict__ gx0, float* __restrict__ gx1, float* __restrict__ gx2,
    int* __restrict__ syn)
{
    extern __shared__ char smraw[];
    const size_t WSZ = (size_t)GATES * HID;
    int* prog0  = syn;
    int* prog1  = syn + 64;
    int* ctr    = syn + 128;
    int* chunk1 = syn + 130;
    int* chunk2 = chunk1 + BATCH * NCHUNK;

    const int bx = blockIdx.x;
    if (bx < BATCH) {
        rec_body(whh, gx0, g_h0hi, g_h0lo, nullptr, prog0, nullptr, bx, smraw);
        __syncthreads();
        rec_body(whh + 2 * WSZ, gx2, nullptr, nullptr, g_h2last,
                 nullptr, chunk2, bx, smraw);
    } else if (bx < 2 * BATCH) {
        rec_body(whh + WSZ, gx1, g_h1hi, g_h1lo, nullptr, prog1, chunk1,
                 bx - BATCH, smraw);
        __syncthreads();
        gemm_worker_unified(bih, bhh, gx1, gx2, prog0, prog1, ctr,
                            chunk1, chunk2, smraw);
    } else {
        gemm_worker_unified(bih, bhh, gx1, gx2, prog0, prog1, ctr,
                            chunk1, chunk2, smraw);
    }
}

// ---------------------------------------------------------------------------
// MLP head: 64 CTAs, one per batch row. h_last[128] -> 64 -> 32 -> 10.
// ---------------------------------------------------------------------------
__global__ __launch_bounds__(256) void mlp_kernel(
    const float* __restrict__ w1, const float* __restrict__ b1,
    const float* __restrict__ w2, const float* __restrict__ b2,
    const float* __restrict__ w3, const float* __restrict__ b3,
    float* __restrict__ out)
{
    __shared__ float hs[128];
    __shared__ float y1[64];
    __shared__ float y2[32];

    const int tid = threadIdx.x;
    const int b   = blockIdx.x;
    if (tid < 128) hs[tid] = g_h2last[b * HID + tid];
    __syncthreads();
    if (tid < 64) {
        float s = b1[tid];
        const float* wr = w1 + tid * 128;
#pragma unroll 16
        for (int k = 0; k < 128; k++) s = fmaf(hs[k], wr[k], s);
        y1[tid] = s;
    }
    __syncthreads();
    if (tid < 32) {
        float s = b2[tid];
        const float* wr = w2 + tid * 64;
#pragma unroll 16
        for (int k = 0; k < 64; k++) s = fmaf(y1[k], wr[k], s);
        y2[tid] = s;
    }
    __syncthreads();
    if (tid < 10) {
        float s = b3[tid];
        const float* wr = w3 + tid * 32;
#pragma unroll
        for (int k = 0; k < 32; k++) s = fmaf(y2[k], wr[k], s);
        out[b * 10 + tid] = s;
    }
}

// ---------------------------------------------------------------------------
extern "C" void kernel_launch(void* const* d_in, const int* in_sizes, int n_in,
                              void* d_out, int out_size)
{
    (void)in_sizes; (void)n_in; (void)out_size;
    const float* x   = (const float*)d_in[0];
    const float* wih = (const float*)d_in[1];
    const float* whh = (const float*)d_in[2];
    const float* bih = (const float*)d_in[3];
    const float* bhh = (const float*)d_in[4];
    const float* w1  = (const float*)d_in[5];
    const float* b1  = (const float*)d_in[6];
    const float* w2  = (const float*)d_in[7];
    const float* b2  = (const float*)d_in[8];
    const float* w3  = (const float*)d_in[9];
    const float* b3  = (const float*)d_in[10];

    void *pA = nullptr, *pB = nullptr, *pS = nullptr;
    void *pxh = nullptr, *pxl = nullptr, *pwh = nullptr, *pwl = nullptr;
    cudaGetSymbolAddress(&pA, g_gxA);
    cudaGetSymbolAddress(&pB, g_gxB);
    cudaGetSymbolAddress(&pS, g_syn);
    cudaGetSymbolAddress(&pxh, g_xhi);
    cudaGetSymbolAddress(&pxl, g_xlo);
    cudaGetSymbolAddress(&pwh, g_whi);
    cudaGetSymbolAddress(&pwl, g_wlo);
    float* bufA = (float*)pA;   // gx0, then gx2
    float* bufB = (float*)pB;   // gx1
    int*   syn  = (int*)pS;

    const int GEMM_SMEM = 4 * 128 * SR * 2 + 128 * 4;   // 139,776 B
    cudaFuncSetAttribute(gemm0_kernel, cudaFuncAttributeMaxDynamicSharedMemorySize, GEMM_SMEM);
    cudaFuncSetAttribute(mega_kernel,  cudaFuncAttributeMaxDynamicSharedMemorySize, GEMM_SMEM);

    cudaMemsetAsync(syn, 0, (130 + 2 * BATCH * NCHUNK) * sizeof(int));

    // Pre-split x and all wih layers into bf16 hi/lo
    const long XN4 = (long)BATCH * T_STEPS * HID / 4;          // 4,194,304
    const long WN4 = (long)3 * GATES * HID / 4;                // 49,152
    split_kernel<<<(unsigned)((XN4 + 255) / 256), 256>>>(
        x, (__nv_bfloat16*)pxh, (__nv_bfloat16*)pxl, XN4);
    split_kernel<<<(unsigned)((WN4 + 255) / 256), 256>>>(
        wih, (__nv_bfloat16*)pwh, (__nv_bfloat16*)pwl, WN4);

    // gx0 = x @ wih0^T + biases  -> bufA
    gemm0_kernel<<<dim3(BATCH * T_STEPS / 128, 4), 256, GEMM_SMEM>>>(bih, bhh);

    // All three rec layers + both inner GEMMs, pipelined per 128-step chunk.
    mega_kernel<<<NSM, 256, GEMM_SMEM>>>(whh, bih, bhh, bufA, bufB, bufA, syn);

    mlp_kernel<<<BATCH, 256>>>(w1, b1, w2, b2, w3, b3, (float*)d_out);
}

// round 17
// speedup vs baseline: 1.4236x; 1.4236x over previous
#include <cuda_runtime.h>
#include <cuda_bf16.h>
#include <cstddef>

#define T_STEPS 2048
#define BATCH   64
#define HID     128
#define GATES   512          // 4*HID
#define RK      96           // k-values in registers (as pairs)
#define RKP     (RK/2)       // 48 register pairs
#define SK      (HID - RK)   // 32 k-values in smem
#define SKP     (SK/2)       // 16 smem pairs
#define NSM     148
#define NCHUNK  16           // 2048 / 128
#define CHSTEP  128
#define NTASKS  (NCHUNK * 4 * 8)   // 512 W-resident tasks per layer

typedef unsigned long long ull;

// ---- packed fp32x2 helpers (sm_100+) --------------------------------------
__device__ __forceinline__ ull ffma2(ull a, ull b, ull c) {
    ull d;
    asm("fma.rn.f32x2 %0, %1, %2, %3;" : "=l"(d) : "l"(a), "l"(b), "l"(c));
    return d;
}
__device__ __forceinline__ ull pack2(float lo, float hi) {
    ull r; asm("mov.b64 %0, {%1, %2};" : "=l"(r) : "f"(lo), "f"(hi)); return r;
}
__device__ __forceinline__ float2 unpack2(ull v) {
    float2 f; asm("mov.b64 {%0, %1}, %2;" : "=f"(f.x), "=f"(f.y) : "l"(v)); return f;
}
__device__ __forceinline__ int ld_acquire_gpu(const int* p) {
    int v;
    asm volatile("ld.acquire.gpu.global.s32 %0, [%1];" : "=r"(v) : "l"(p) : "memory");
    return v;
}

// Scratch (device globals; no allocations allowed)
__device__ float g_gxA[(size_t)BATCH * T_STEPS * GATES];  // gx0, then reused for gx2
__device__ float g_gxB[(size_t)BATCH * T_STEPS * GATES];  // gx1
__device__ __nv_bfloat16 g_xhi[(size_t)BATCH * T_STEPS * HID];  // x split
__device__ __nv_bfloat16 g_xlo[(size_t)BATCH * T_STEPS * HID];
__device__ __nv_bfloat16 g_h0hi[(size_t)BATCH * T_STEPS * HID]; // h0 split
__device__ __nv_bfloat16 g_h0lo[(size_t)BATCH * T_STEPS * HID];
__device__ __nv_bfloat16 g_h1hi[(size_t)BATCH * T_STEPS * HID]; // h1 split
__device__ __nv_bfloat16 g_h1lo[(size_t)BATCH * T_STEPS * HID];
__device__ __nv_bfloat16 g_whi[3 * GATES * HID];                // wih split (3 layers)
__device__ __nv_bfloat16 g_wlo[3 * GATES * HID];
__device__ float g_h2last[BATCH * HID];
__device__ int   g_syn[132 + BATCH * NCHUNK * 2];  // prog0[64] prog1[64] ctr1 ctr2 chunk1 chunk2

// ---------------------------------------------------------------------------
// fp32 -> (bf16 hi, bf16 lo) splitter, vectorized 4 elements/thread
// ---------------------------------------------------------------------------
__global__ __launch_bounds__(256) void split_kernel(
    const float* __restrict__ src, __nv_bfloat16* __restrict__ hi,
    __nv_bfloat16* __restrict__ lo, long n4)
{
    long i = (long)blockIdx.x * 256 + threadIdx.x;
    if (i >= n4) return;
    float4 v = ((const float4*)src)[i];
    __nv_bfloat16 h0 = __float2bfloat16_rn(v.x);
    __nv_bfloat16 h1 = __float2bfloat16_rn(v.y);
    __nv_bfloat16 h2 = __float2bfloat16_rn(v.z);
    __nv_bfloat16 h3 = __float2bfloat16_rn(v.w);
    __nv_bfloat162 H0; H0.x = h0; H0.y = h1;
    __nv_bfloat162 H1; H1.x = h2; H1.y = h3;
    __nv_bfloat162 L0 = __floats2bfloat162_rn(v.x - __bfloat162float(h0),
                                              v.y - __bfloat162float(h1));
    __nv_bfloat162 L1 = __floats2bfloat162_rn(v.z - __bfloat162float(h2),
                                              v.w - __bfloat162float(h3));
    ((__nv_bfloat162*)hi)[2 * i]     = H0;
    ((__nv_bfloat162*)hi)[2 * i + 1] = H1;
    ((__nv_bfloat162*)lo)[2 * i]     = L0;
    ((__nv_bfloat162*)lo)[2 * i + 1] = L1;
}

// ---------------------------------------------------------------------------
// GEMM tile machinery (pre-split bf16 inputs, fp32 acc, ldmatrix)
// ---------------------------------------------------------------------------
#define SR 136   // padded bf16 row stride

__device__ __forceinline__ void mma_bf16(float* d, const unsigned* a, const unsigned* b) {
    asm volatile(
        "mma.sync.aligned.m16n8k16.row.col.f32.bf16.bf16.f32 "
        "{%0,%1,%2,%3}, {%4,%5,%6,%7}, {%8,%9}, {%0,%1,%2,%3};"
        : "+f"(d[0]), "+f"(d[1]), "+f"(d[2]), "+f"(d[3])
        : "r"(a[0]), "r"(a[1]), "r"(a[2]), "r"(a[3]), "r"(b[0]), "r"(b[1]));
}
__device__ __forceinline__ void ldsm_x4(unsigned* r, unsigned addr) {
    asm volatile("ldmatrix.sync.aligned.m8n8.x4.shared.b16 {%0,%1,%2,%3}, [%4];"
                 : "=r"(r[0]), "=r"(r[1]), "=r"(r[2]), "=r"(r[3]) : "r"(addr));
}

// smem layout helpers (gsm = dynamic smem base)
// [a_hi 128*SR][a_lo 128*SR][w_hi 128*SR][w_lo 128*SR][bias 128]
__device__ __forceinline__ __nv_bfloat16* SM_AHI(char* g) { return (__nv_bfloat16*)g; }
__device__ __forceinline__ __nv_bfloat16* SM_ALO(char* g) { return (__nv_bfloat16*)g + 128 * SR; }
__device__ __forceinline__ __nv_bfloat16* SM_WHI(char* g) { return (__nv_bfloat16*)g + 2 * 128 * SR; }
__device__ __forceinline__ __nv_bfloat16* SM_WLO(char* g) { return (__nv_bfloat16*)g + 3 * 128 * SR; }
__device__ __forceinline__ float*         SM_BIAS(char* g){ return (float*)((__nv_bfloat16*)g + 4 * 128 * SR); }

// Copy one 128x128 bf16 W tile (hi+lo) + bias into smem
__device__ void copy_W(const __nv_bfloat16* __restrict__ Whi,
                       const __nv_bfloat16* __restrict__ Wlo,
                       const float* __restrict__ bih, const float* __restrict__ bhh,
                       int bcol, char* gsm)
{
    const int tid = threadIdx.x;
    if (tid < 128) SM_BIAS(gsm)[tid] = bih[bcol + tid] + bhh[bcol + tid];
    const int row = tid >> 1;
    const int cb  = (tid & 1) * 64;
    const uint4* sWh = (const uint4*)(Whi + (size_t)(bcol + row) * HID + cb);
    const uint4* sWl = (const uint4*)(Wlo + (size_t)(bcol + row) * HID + cb);
    uint4* dWh = (uint4*)(SM_WHI(gsm) + row * SR + cb);
    uint4* dWl = (uint4*)(SM_WLO(gsm) + row * SR + cb);
#pragma unroll
    for (int i = 0; i < 8; i++) { dWh[i] = sWh[i]; dWl[i] = sWl[i]; }
}

// Copy one 128x128 bf16 A tile (hi+lo) into smem
__device__ void copy_A(const __nv_bfloat16* __restrict__ Ahi,
                       const __nv_bfloat16* __restrict__ Alo,
                       int brow, char* gsm)
{
    const int tid = threadIdx.x;
    const int row = tid >> 1;
    const int cb  = (tid & 1) * 64;
    const uint4* sAh = (const uint4*)(Ahi + (size_t)(brow + row) * HID + cb);
    const uint4* sAl = (const uint4*)(Alo + (size_t)(brow + row) * HID + cb);
    uint4* dAh = (uint4*)(SM_AHI(gsm) + row * SR + cb);
    uint4* dAl = (uint4*)(SM_ALO(gsm) + row * SR + cb);
#pragma unroll
    for (int i = 0; i < 8; i++) { dAh[i] = sAh[i]; dAl[i] = sAl[i]; }
}

// mma + epilogue (reads smem only; W/A must be loaded and synced)
__device__ void mma_store(float* __restrict__ out, int brow, int bcol, char* gsm)
{
    const int tid    = threadIdx.x;
    const int wid    = tid >> 5;
    const int lane   = tid & 31;
    const int warp_m = wid >> 1;
    const int warp_n = wid & 1;
    const int m_base = warp_m * 32;
    const int n_base = warp_n * 64;

    const unsigned a_hi_s = (unsigned)__cvta_generic_to_shared(SM_AHI(gsm));
    const unsigned a_lo_s = (unsigned)__cvta_generic_to_shared(SM_ALO(gsm));
    const unsigned w_hi_s = (unsigned)__cvta_generic_to_shared(SM_WHI(gsm));
    const unsigned w_lo_s = (unsigned)__cvta_generic_to_shared(SM_WLO(gsm));
    float* bias_s = SM_BIAS(gsm);

    const int arow  = m_base + (lane & 15);
    const int akoff = (lane >> 4) * 8;
    const int gsel  = lane >> 3;
    const int brow_ = n_base + ((gsel >> 1) & 1) * 8 + (lane & 7);
    const int bkoff = (gsel & 1) * 8;

    float d[2][8][4];
#pragma unroll
    for (int mi = 0; mi < 2; mi++)
#pragma unroll
        for (int ni = 0; ni < 8; ni++)
#pragma unroll
            for (int e = 0; e < 4; e++) d[mi][ni][e] = 0.f;

#pragma unroll
    for (int k0 = 0; k0 < HID; k0 += 16) {
        unsigned ah[2][4], al[2][4];
#pragma unroll
        for (int mi = 0; mi < 2; mi++) {
            unsigned off = (unsigned)(((arow + mi * 16) * SR + akoff + k0) * 2);
            ldsm_x4(ah[mi], a_hi_s + off);
            ldsm_x4(al[mi], a_lo_s + off);
        }
        unsigned bh[4][4], bl[4][4];
#pragma unroll
        for (int nb = 0; nb < 4; nb++) {
            unsigned off = (unsigned)(((brow_ + nb * 16) * SR + bkoff + k0) * 2);
            ldsm_x4(bh[nb], w_hi_s + off);
            ldsm_x4(bl[nb], w_lo_s + off);
        }
#pragma unroll
        for (int mi = 0; mi < 2; mi++)
#pragma unroll
            for (int nb = 0; nb < 4; nb++) {
                mma_bf16(d[mi][2 * nb],     ah[mi], &bh[nb][0]);
                mma_bf16(d[mi][2 * nb],     ah[mi], &bl[nb][0]);
                mma_bf16(d[mi][2 * nb],     al[mi], &bh[nb][0]);
                mma_bf16(d[mi][2 * nb + 1], ah[mi], &bh[nb][2]);
                mma_bf16(d[mi][2 * nb + 1], ah[mi], &bl[nb][2]);
                mma_bf16(d[mi][2 * nb + 1], al[mi], &bh[nb][2]);
            }
    }

    const int tr = lane >> 2;
    const int tc = (lane & 3) * 2;
#pragma unroll
    for (int mi = 0; mi < 2; mi++) {
        int gr0 = brow + m_base + mi * 16 + tr;
#pragma unroll
        for (int ni = 0; ni < 8; ni++) {
            int lc = n_base + ni * 8 + tc;
            float2 bv = *(const float2*)&bias_s[lc];
            float2 o0 = {d[mi][ni][0] + bv.x, d[mi][ni][1] + bv.y};
            float2 o1 = {d[mi][ni][2] + bv.x, d[mi][ni][3] + bv.y};
            *(float2*)(out + (size_t)gr0 * GATES + bcol + lc)       = o0;
            *(float2*)(out + (size_t)(gr0 + 8) * GATES + bcol + lc) = o1;
        }
    }
}

// Standalone layer-0 GEMM over the whole (pre-split) input: one tile per CTA
__global__ __launch_bounds__(256) void gemm0_kernel(
    const float* __restrict__ bih, const float* __restrict__ bhh)
{
    extern __shared__ char gsm[];
    int brow = blockIdx.x * 128, bcol = blockIdx.y * 128;
    copy_W(g_whi, g_wlo, bih, bhh, bcol, gsm);
    copy_A(g_xhi, g_xlo, brow, gsm);
    __syncthreads();
    mma_store(g_gxA, brow, bcol, gsm);
}

// ---------------------------------------------------------------------------
// Recurrence body (R3 structure, measured best).
// ---------------------------------------------------------------------------
__device__ __forceinline__ float sigm(float x) {
    return __fdividef(1.f, 1.f + __expf(-x));
}
__device__ __forceinline__ float tanh_fast(float x) {
    float e = __expf(2.f * x);
    return 1.f - __fdividef(2.f, e + 1.f);
}

__device__ void rec_body(const float* __restrict__ whh, const float* __restrict__ gx,
                         __nv_bfloat16* __restrict__ hhi, __nv_bfloat16* __restrict__ hlo,
                         float* __restrict__ hlast,
                         int* __restrict__ prog, const int* __restrict__ chunkready,
                         int b, char* smraw)
{
    ull*   ws2 = (ull*)smraw;                    // [SKP][512] pair-major weight pairs
    float* g_s = (float*)(ws2 + SKP * 512);      // 512 gate pre-activations
    float* h_s = g_s + GATES;                    // 128 hidden state

    const int tid = threadIdx.x;
    const int r0  = tid;
    const int r1  = tid + 256;

    ull wa2[RKP], wb2[RKP];
    {
        const ull* wp0 = (const ull*)(whh + (size_t)r0 * HID);
        const ull* wp1 = (const ull*)(whh + (size_t)r1 * HID);
#pragma unroll
        for (int q = 0; q < RKP; q++) { wa2[q] = wp0[q]; wb2[q] = wp1[q]; }
    }
    for (int idx = tid; idx < SKP * 512; idx += 256) {
        int r = idx & 511, p = idx >> 9;
        ws2[idx] = ((const ull*)(whh + (size_t)r * HID))[RKP + p];
    }
    if (tid < HID) h_s[tid] = 0.f;
    float c = 0.f;
    __syncthreads();

    const float* gxb = gx + (size_t)b * T_STEPS * GATES;
    __nv_bfloat16* hhib = hhi ? hhi + (size_t)b * T_STEPS * HID : nullptr;
    __nv_bfloat16* hlob = hlo ? hlo + (size_t)b * T_STEPS * HID : nullptr;

    float nga = 0.f, ngb = 0.f;
    if (!chunkready) { nga = gxb[r0]; ngb = gxb[r1]; }

    for (int t = 0; t < T_STEPS; t++) {
        if (chunkready && (t & (CHSTEP - 1)) == 0) {
            if (tid == 0) {
                const int* cw = chunkready + b * NCHUNK + (t >> 7);
                while (ld_acquire_gpu(cw) < 4) __nanosleep(128);
            }
            __syncthreads();
            nga = __ldg(gxb + (size_t)t * GATES + r0);
            ngb = __ldg(gxb + (size_t)t * GATES + r1);
        }
        ull acc0 = pack2(nga, 0.f);
        ull acc1 = pack2(ngb, 0.f);
        if (t + 1 < T_STEPS && (!chunkready || ((t + 1) & (CHSTEP - 1)) != 0)) {
            nga = __ldg(gxb + (size_t)(t + 1) * GATES + r0);
            ngb = __ldg(gxb + (size_t)(t + 1) * GATES + r1);
        }
        const ull* h2 = (const ull*)h_s;   // 64 packed h pairs (broadcast LDS.64)
#pragma unroll
        for (int q = 0; q < RKP; q++) {
            ull hp = h2[q];
            acc0 = ffma2(hp, wa2[q], acc0);
            acc1 = ffma2(hp, wb2[q], acc1);
        }
#pragma unroll
        for (int p = 0; p < SKP; p++) {
            ull hp = h2[RKP + p];
            acc0 = ffma2(hp, ws2[p * 512 + r0], acc0);
            acc1 = ffma2(hp, ws2[p * 512 + r1], acc1);
        }
        float2 v0 = unpack2(acc0);
        float2 v1 = unpack2(acc1);
        g_s[r0] = v0.x + v0.y;
        g_s[r1] = v1.x + v1.y;
        __syncthreads();
        if (tid < 128) {
            float i_ = sigm(g_s[tid]);
            float f_ = sigm(g_s[tid + 128]);
            float g_ = tanh_fast(g_s[tid + 256]);
            float o_ = sigm(g_s[tid + 384]);
            c = fmaf(f_, c, i_ * g_);
            float hv = o_ * tanh_fast(c);
            h_s[tid] = hv;
            if (hhib) {
                __nv_bfloat16 hb16 = __float2bfloat16_rn(hv);
                hhib[(size_t)t * HID + tid] = hb16;
                hlob[(size_t)t * HID + tid] =
                    __float2bfloat16_rn(hv - __bfloat162float(hb16));
            }
            if (hlast && t == T_STEPS - 1) hlast[b * HID + tid] = hv;
        }
        bool pub = prog && ((t & 63) == 63);
        if (pub) __threadfence();          // all threads: release h writes
        __syncthreads();
        if (pub && tid == 0) atomicExch(prog + b, t + 1);
    }
}

// ---------------------------------------------------------------------------
// W-resident GEMM pool: task = (chunk, cy, bgroup-of-8). Worker loads W(cy)
// once, then streams 8 per-b-gated A tiles against it. Tasks chunk-major.
// ---------------------------------------------------------------------------
__device__ void gemm_pool(const __nv_bfloat16* __restrict__ Hhi,
                          const __nv_bfloat16* __restrict__ Hlo,
                          const __nv_bfloat16* __restrict__ Whi,
                          const __nv_bfloat16* __restrict__ Wlo,
                          const float* __restrict__ bih, const float* __restrict__ bhh,
                          float* __restrict__ out,
                          int* __restrict__ prog, int* __restrict__ ctr,
                          int* __restrict__ chunkdone, char* gsm)
{
    const int tid = threadIdx.x;
    __shared__ int s_idx;
    while (true) {
        if (tid == 0) s_idx = atomicAdd(ctr, 1);
        __syncthreads();
        int idx = s_idx;
        __syncthreads();
        if (idx >= NTASKS) break;
        int chunk = idx >> 5;            // 0..15
        int rem   = idx & 31;
        int cy    = rem >> 3;            // 0..3
        int bg    = rem & 7;             // 0..7

        copy_W(Whi, Wlo, bih, bhh, cy * 128, gsm);
        __syncthreads();

        for (int bs = 0; bs < 8; bs++) {
            int b = bg * 8 + bs;
            if (tid == 0) {
                int need = (chunk + 1) * CHSTEP;
                int v;
                while (true) {
                    asm volatile("ld.global.cg.u32 %0, [%1];" : "=r"(v) : "l"(prog + b));
                    if (v >= need) break;
                    __nanosleep(256);
                }
                __threadfence();
            }
            __syncthreads();
            int brow = b * T_STEPS + chunk * CHSTEP;
            copy_A(Hhi, Hlo, brow, gsm);
            __syncthreads();
            mma_store(out, brow, cy * 128, gsm);
            __threadfence();             // release tile stores
            __syncthreads();
            if (tid == 0) atomicAdd(chunkdone + b * NCHUNK + chunk, 1);
            __syncthreads();             // compute done before next A overwrite
        }
        __syncthreads();                 // before next task's W overwrite
    }
}

// ---------------------------------------------------------------------------
// Mega kernel (sequential pools, R15 structure + rec0 CTAs help gemm1):
//  blocks [0,64):    rec0 (prog0) -> gemm1 pool -> rec2 (gated chunk2)
//  blocks [64,128):  rec1 (gated chunk1, prog1) -> gemm2 pool
//  blocks [128,148): gemm1 pool -> gemm2 pool
// gx2 aliases gx0's buffer — safe by the causal chain
// prog1>=128(k+1) => rec1 consumed gx1[k] => gemm1[k] done =>
// prog0>=128(k+1) => rec0 finished reading gx0[k].
// ---------------------------------------------------------------------------
__global__ __launch_bounds__(256, 1) void mega_kernel(
    const float* __restrict__ whh,
    const float* __restrict__ bih, const float* __restrict__ bhh,
    float* __restrict__ gx0, float* __restrict__ gx1, float* __restrict__ gx2,
    int* __restrict__ syn)
{
    extern __shared__ char smraw[];
    const size_t WSZ = (size_t)GATES * HID;
    int* prog0  = syn;
    int* prog1  = syn + 64;
    int* ctr1   = syn + 128;
    int* ctr2   = syn + 129;
    int* chunk1 = syn + 132;
    int* chunk2 = chunk1 + BATCH * NCHUNK;

    const int bx = blockIdx.x;
    if (bx < BATCH) {
        rec_body(whh, gx0, g_h0hi, g_h0lo, nullptr, prog0, nullptr, bx, smraw);
        __syncthreads();
        gemm_pool(g_h0hi, g_h0lo, g_whi + WSZ, g_wlo + WSZ, bih + GATES,
                  bhh + GATES, gx1, prog0, ctr1, chunk1, smraw);
        __syncthreads();
        rec_body(whh + 2 * WSZ, gx2, nullptr, nullptr, g_h2last,
                 nullptr, chunk2, bx, smraw);
    } else if (bx < 2 * BATCH) {
        rec_body(whh + WSZ, gx1, g_h1hi, g_h1lo, nullptr, prog1, chunk1,
                 bx - BATCH, smraw);
        __syncthreads();
        gemm_pool(g_h1hi, g_h1lo, g_whi + 2 * WSZ, g_wlo + 2 * WSZ,
                  bih + 2 * GATES, bhh + 2 * GATES, gx2, prog1, ctr2, chunk2, smraw);
    } else {
        gemm_pool(g_h0hi, g_h0lo, g_whi + WSZ, g_wlo + WSZ, bih + GATES,
                  bhh + GATES, gx1, prog0, ctr1, chunk1, smraw);
        __syncthreads();
        gemm_pool(g_h1hi, g_h1lo, g_whi + 2 * WSZ, g_wlo + 2 * WSZ,
                  bih + 2 * GATES, bhh + 2 * GATES, gx2, prog1, ctr2, chunk2, smraw);
    }
}

// ---------------------------------------------------------------------------
// MLP head: 64 CTAs, one per batch row. h_last[128] -> 64 -> 32 -> 10.
// ---------------------------------------------------------------------------
__global__ __launch_bounds__(256) void mlp_kernel(
    const float* __restrict__ w1, const float* __restrict__ b1,
    const float* __restrict__ w2, const float* __restrict__ b2,
    const float* __restrict__ w3, const float* __restrict__ b3,
    float* __restrict__ out)
{
    __shared__ float hs[128];
    __shared__ float y1[64];
    __shared__ float y2[32];

    const int tid = threadIdx.x;
    const int b   = blockIdx.x;
    if (tid < 128) hs[tid] = g_h2last[b * HID + tid];
    __syncthreads();
    if (tid < 64) {
        float s = b1[tid];
        const float* wr = w1 + tid * 128;
#pragma unroll 16
        for (int k = 0; k < 128; k++) s = fmaf(hs[k], wr[k], s);
        y1[tid] = s;
    }
    __syncthreads();
    if (tid < 32) {
        float s = b2[tid];
        const float* wr = w2 + tid * 64;
#pragma unroll 16
        for (int k = 0; k < 64; k++) s = fmaf(y1[k], wr[k], s);
        y2[tid] = s;
    }
    __syncthreads();
    if (tid < 10) {
        float s = b3[tid];
        const float* wr = w3 + tid * 32;
#pragma unroll
        for (int k = 0; k < 32; k++) s = fmaf(y2[k], wr[k], s);
        out[b * 10 + tid] = s;
    }
}

// ---------------------------------------------------------------------------
extern "C" void kernel_launch(void* const* d_in, const int* in_sizes, int n_in,
                              void* d_out, int out_size)
{
    (void)in_sizes; (void)n_in; (void)out_size;
    const float* x   = (const float*)d_in[0];
    const float* wih = (const float*)d_in[1];
    const float* whh = (const float*)d_in[2];
    const float* bih = (const float*)d_in[3];
    const float* bhh = (const float*)d_in[4];
    const float* w1  = (const float*)d_in[5];
    const float* b1  = (const float*)d_in[6];
    const float* w2  = (const float*)d_in[7];
    const float* b2  = (const float*)d_in[8];
    const float* w3  = (const float*)d_in[9];
    const float* b3  = (const float*)d_in[10];

    void *pA = nullptr, *pB = nullptr, *pS = nullptr;
    void *pxh = nullptr, *pxl = nullptr, *pwh = nullptr, *pwl = nullptr;
    cudaGetSymbolAddress(&pA, g_gxA);
    cudaGetSymbolAddress(&pB, g_gxB);
    cudaGetSymbolAddress(&pS, g_syn);
    cudaGetSymbolAddress(&pxh, g_xhi);
    cudaGetSymbolAddress(&pxl, g_xlo);
    cudaGetSymbolAddress(&pwh, g_whi);
    cudaGetSymbolAddress(&pwl, g_wlo);
    float* bufA = (float*)pA;   // gx0, then gx2
    float* bufB = (float*)pB;   // gx1
    int*   syn  = (int*)pS;

    const int GEMM_SMEM = 4 * 128 * SR * 2 + 128 * 4;   // 139,776 B
    cudaFuncSetAttribute(gemm0_kernel, cudaFuncAttributeMaxDynamicSharedMemorySize, GEMM_SMEM);
    cudaFuncSetAttribute(mega_kernel,  cudaFuncAttributeMaxDynamicSharedMemorySize, GEMM_SMEM);

    cudaMemsetAsync(syn, 0, (132 + 2 * BATCH * NCHUNK) * sizeof(int));

    // Pre-split x and all wih layers into bf16 hi/lo
    const long XN4 = (long)BATCH * T_STEPS * HID / 4;          // 4,194,304
    const long WN4 = (long)3 * GATES * HID / 4;                // 49,152
    split_kernel<<<(unsigned)((XN4 + 255) / 256), 256>>>(
        x, (__nv_bfloat16*)pxh, (__nv_bfloat16*)pxl, XN4);
    split_kernel<<<(unsigned)((WN4 + 255) / 256), 256>>>(
        wih, (__nv_bfloat16*)pwh, (__nv_bfloat16*)pwl, WN4);

    // gx0 = x @ wih0^T + biases  -> bufA
    gemm0_kernel<<<dim3(BATCH * T_STEPS / 128, 4), 256, GEMM_SMEM>>>(bih, bhh);

    // All three rec layers + both inner GEMMs, pipelined per 128-step chunk.
    mega_kernel<<<NSM, 256, GEMM_SMEM>>>(whh, bih, bhh, bufA, bufB, bufA, syn);

    mlp_kernel<<<BATCH, 256>>>(w1, b1, w2, b2, w3, b3, (float*)d_out);
}